// round 1
// baseline (speedup 1.0000x reference)
#include <cuda_runtime.h>
#include <math.h>

// Intermediate activations (static device globals — no runtime allocation).
__device__ float g_a1[32*50*32*64];    // after L1 (conv+pool+relu)   [32,50,32,64]
__device__ float g_a2[32*50*16*16];    // after L2 (conv+pool+relu)   [32,50,16,16]
__device__ float g_a2c[16*50*16*16];   // after combine               [16,50,16,16]
__device__ float g_a3[16*50*32*64];    // after L3 (up+conv+relu)     [16,50,32,64]
__device__ float g_a4[16*50*64*256];   // after L4 (up+conv+relu)     [16,50,64,256]

// ---------------------------------------------------------------------------
// K1: circular conv1 (1->50, 3x7 on 64x256) + maxpool(2,4) + relu
// grid (8 strips, 32 batch), 256 threads. Strip = 4 pooled rows = 8 conv rows.
// ---------------------------------------------------------------------------
__global__ void k1(const float* __restrict__ x, const float* __restrict__ w1,
                   const float* __restrict__ b1) {
    __shared__ float sx[10][256];
    __shared__ float sw[50*21];
    const int b = blockIdx.y, strip = blockIdx.x;
    const int tid = threadIdx.x;
    const float* xb = x + b*64*256;
    for (int idx = tid; idx < 10*256; idx += 256) {
        int l = idx >> 8, col = idx & 255;
        int row = (strip*8 - 2 + l) & 63;
        sx[l][col] = xb[row*256 + col];
    }
    for (int idx = tid; idx < 1050; idx += 256) sw[idx] = w1[idx];
    __syncthreads();

    const int prl = tid >> 6;          // pooled row within strip 0..3
    const int pw  = tid & 63;          // pooled col 0..63
    float xv[4][10];
    #pragma unroll
    for (int rl = 0; rl < 4; rl++)
        #pragma unroll
        for (int j = 0; j < 10; j++)
            xv[rl][j] = sx[prl*2 + rl][(pw*4 - 6 + j) & 255];

    const int pr = strip*4 + prl;
    for (int co = 0; co < 50; co++) {
        float acc[8];
        #pragma unroll
        for (int i = 0; i < 8; i++) acc[i] = 0.f;
        #pragma unroll
        for (int p = 0; p < 3; p++)
            #pragma unroll
            for (int q = 0; q < 7; q++) {
                float wv = sw[co*21 + p*7 + q];
                #pragma unroll
                for (int dr = 0; dr < 2; dr++)
                    #pragma unroll
                    for (int dc = 0; dc < 4; dc++)
                        acc[dr*4+dc] += wv * xv[dr + 2 - p][dc + 6 - q];
            }
        float m = acc[0];
        #pragma unroll
        for (int i = 1; i < 8; i++) m = fmaxf(m, acc[i]);
        g_a1[((b*50 + co)*32 + pr)*64 + pw] = fmaxf(m + b1[co], 0.f);
    }
}

// ---------------------------------------------------------------------------
// K2: circular conv2 (50->50, 3x7 on 32x64) + maxpool(2,4) + relu
// grid (16 pooled rows, 32 batch), 256 threads = (16 pw, 16 ty).
// co coverage: ty 0,1 -> 4 couts; ty 2..15 -> 3 couts (exactly 50, no waste).
// ---------------------------------------------------------------------------
__global__ void k2(const float* __restrict__ w2, const float* __restrict__ b2) {
    __shared__ float sx[25][4][64];
    const int b = blockIdx.y, r = blockIdx.x;
    const int tid = threadIdx.x;
    const int pw = tid & 15, ty = tid >> 4;

    float acc[4][8];
    #pragma unroll
    for (int s = 0; s < 4; s++)
        #pragma unroll
        for (int i = 0; i < 8; i++) acc[s][i] = 0.f;

    for (int cb = 0; cb < 50; cb += 25) {
        __syncthreads();
        for (int idx = tid; idx < 25*4*64; idx += 256) {
            int cl = idx >> 8, l = (idx >> 6) & 3, col = idx & 63;
            int row = (2*r - 2 + l) & 31;
            sx[cl][l][col] = g_a1[((b*50 + cb + cl)*32 + row)*64 + col];
        }
        __syncthreads();
        for (int cl = 0; cl < 25; cl++) {
            float xv[4][10];
            #pragma unroll
            for (int l = 0; l < 4; l++)
                #pragma unroll
                for (int j = 0; j < 10; j++)
                    xv[l][j] = sx[cl][l][(pw*4 - 6 + j) & 63];
            #pragma unroll
            for (int s = 0; s < 4; s++) {
                int co = ty + s*16;
                if (co < 50) {
                    const float* wp = w2 + (co*50 + cb + cl)*21;
                    #pragma unroll
                    for (int p = 0; p < 3; p++)
                        #pragma unroll
                        for (int q = 0; q < 7; q++) {
                            float wv = __ldg(&wp[p*7 + q]);
                            #pragma unroll
                            for (int dr = 0; dr < 2; dr++)
                                #pragma unroll
                                for (int dc = 0; dc < 4; dc++)
                                    acc[s][dr*4+dc] += wv * xv[dr + 2 - p][dc + 6 - q];
                        }
                }
            }
        }
    }
    #pragma unroll
    for (int s = 0; s < 4; s++) {
        int co = ty + s*16;
        if (co < 50) {
            float m = acc[s][0];
            #pragma unroll
            for (int i = 1; i < 8; i++) m = fmaxf(m, acc[s][i]);
            g_a2[((b*50 + co)*16 + r)*16 + pw] = fmaxf(m + b2[co], 0.f);
        }
    }
}

// ---------------------------------------------------------------------------
// K3: combine: out[b] = a2[2b] + mean_{hw}(a2[2b+1]).  grid 800 = 16*50.
// ---------------------------------------------------------------------------
__global__ void k3() {
    const int bc = blockIdx.x;
    const int b = bc / 50, c = bc % 50;
    const int t = threadIdx.x;
    const float* ev = g_a2 + ((2*b)*50 + c)*256;
    const float* od = g_a2 + ((2*b + 1)*50 + c)*256;
    __shared__ float red[256];
    red[t] = od[t];
    __syncthreads();
    for (int s = 128; s > 0; s >>= 1) {
        if (t < s) red[t] += red[t + s];
        __syncthreads();
    }
    float mean = red[0] * (1.f/256.f);
    g_a2c[(b*50 + c)*256 + t] = ev[t] + mean;
}

// ---------------------------------------------------------------------------
// K4: zero-upsample(2,4) + circular conv3 (50->50, 3x5 on 32x64) + relu.
// Sparsity: only taps with (h-p) even and (w-q)%4==0 contribute.
// grid (32 h, 16 b), 256 threads = (64 w, 4 ty). co = ty + 4*kc.
// ---------------------------------------------------------------------------
__global__ void k4(const float* __restrict__ w3, const float* __restrict__ b3) {
    __shared__ float sxd[50][2][16];
    const int b = blockIdx.y, h = blockIdx.x;
    const int tid = threadIdx.x;
    const int hodd = h & 1;
    const int pA = hodd ? 1 : 0;
    const int rowA = ((h - pA) & 31) >> 1;
    const int rowB = ((h - 2) & 31) >> 1;
    for (int idx = tid; idx < 1600; idx += 256) {
        int cin = idx >> 5, slot = (idx >> 4) & 1, col = idx & 15;
        int row = slot ? rowB : rowA;
        sxd[cin][slot][col] = g_a2c[((b*50 + cin)*16 + row)*16 + col];
    }
    __syncthreads();

    const int w = tid & 63, ty = tid >> 6;
    const int np = hodd ? 1 : 2;
    const int cls = w & 3;
    const int nq = (cls == 0) ? 2 : 1;
    const int q0 = cls, q1 = 4;
    const int col0 = ((w - q0) & 63) >> 2;
    const int col1 = ((w - q1) & 63) >> 2;

    float acc[13];
    #pragma unroll
    for (int i = 0; i < 13; i++) acc[i] = 0.f;

    for (int cin = 0; cin < 50; cin++) {
        float x00 = sxd[cin][0][col0];
        float x01 = sxd[cin][0][col1];
        float x10 = sxd[cin][1][col0];
        float x11 = sxd[cin][1][col1];
        #pragma unroll
        for (int kc = 0; kc < 13; kc++) {
            int co = ty + kc*4;
            if (co < 50) {
                const float* wp = w3 + (co*50 + cin)*15;
                float a = acc[kc];
                a += __ldg(&wp[pA*5 + q0]) * x00;
                if (nq == 2) a += __ldg(&wp[pA*5 + q1]) * x01;
                if (np == 2) {
                    a += __ldg(&wp[10 + q0]) * x10;
                    if (nq == 2) a += __ldg(&wp[10 + q1]) * x11;
                }
                acc[kc] = a;
            }
        }
    }
    #pragma unroll
    for (int kc = 0; kc < 13; kc++) {
        int co = ty + kc*4;
        if (co < 50)
            g_a3[((b*50 + co)*32 + h)*64 + w] = fmaxf(acc[kc] + b3[co], 0.f);
    }
}

// ---------------------------------------------------------------------------
// K5: zero-upsample(2,4) + circular conv4 (50->50, 3x7 on 64x256) + relu.
// grid (64 h, 16 b), 256 threads = (64 tx, 4 ty); each thread covers
// w = tx + 64k (k=0..3) -> same w%4 class -> shared weight taps (4 FMA/weight).
// ---------------------------------------------------------------------------
__global__ void k5(const float* __restrict__ w4, const float* __restrict__ b4) {
    __shared__ float sxd[50][2][64];
    const int b = blockIdx.y, h = blockIdx.x;
    const int tid = threadIdx.x;
    const int hodd = h & 1;
    const int pA = hodd ? 1 : 0;
    const int rowA = ((h - pA) & 63) >> 1;
    const int rowB = ((h - 2) & 63) >> 1;
    for (int idx = tid; idx < 6400; idx += 256) {
        int cin = idx >> 7, slot = (idx >> 6) & 1, col = idx & 63;
        int row = slot ? rowB : rowA;
        sxd[cin][slot][col] = g_a3[((b*50 + cin)*32 + row)*64 + col];
    }
    __syncthreads();

    const int tx = tid & 63, ty = tid >> 6;
    const int np = hodd ? 1 : 2;
    const int cls = tx & 3;
    const int nq = (cls <= 2) ? 2 : 1;
    const int q0 = cls, q1 = cls + 4;
    int c0[4], c1[4];
    #pragma unroll
    for (int k = 0; k < 4; k++) {
        c0[k] = ((tx + 64*k - q0) & 255) >> 2;
        c1[k] = ((tx + 64*k - q1) & 255) >> 2;
    }

    float acc[13][4];
    #pragma unroll
    for (int i = 0; i < 13; i++)
        #pragma unroll
        for (int k = 0; k < 4; k++) acc[i][k] = 0.f;

    for (int cin = 0; cin < 50; cin++) {
        float xA0[4], xA1[4], xB0[4], xB1[4];
        #pragma unroll
        for (int k = 0; k < 4; k++) {
            xA0[k] = sxd[cin][0][c0[k]];
            xA1[k] = sxd[cin][0][c1[k]];
            xB0[k] = sxd[cin][1][c0[k]];
            xB1[k] = sxd[cin][1][c1[k]];
        }
        #pragma unroll
        for (int kc = 0; kc < 13; kc++) {
            int co = ty + kc*4;
            if (co < 50) {
                const float* wp = w4 + (co*50 + cin)*21;
                float wv = __ldg(&wp[pA*7 + q0]);
                #pragma unroll
                for (int k = 0; k < 4; k++) acc[kc][k] += wv * xA0[k];
                if (nq == 2) {
                    wv = __ldg(&wp[pA*7 + q1]);
                    #pragma unroll
                    for (int k = 0; k < 4; k++) acc[kc][k] += wv * xA1[k];
                }
                if (np == 2) {
                    wv = __ldg(&wp[14 + q0]);
                    #pragma unroll
                    for (int k = 0; k < 4; k++) acc[kc][k] += wv * xB0[k];
                    if (nq == 2) {
                        wv = __ldg(&wp[14 + q1]);
                        #pragma unroll
                        for (int k = 0; k < 4; k++) acc[kc][k] += wv * xB1[k];
                    }
                }
            }
        }
    }
    #pragma unroll
    for (int kc = 0; kc < 13; kc++) {
        int co = ty + kc*4;
        if (co < 50) {
            float bb = b4[co];
            #pragma unroll
            for (int k = 0; k < 4; k++)
                g_a4[((b*50 + co)*64 + h)*256 + tx + 64*k] =
                    fmaxf(acc[kc][k] + bb, 0.f);
        }
    }
}

// ---------------------------------------------------------------------------
// K6: circular conv5 (50->1, 3x7 on 64x256) + sigmoid.
// grid (64 h, 16 b), 256 threads (w). cin chunked by 10 through smem.
// ---------------------------------------------------------------------------
__global__ void k6(const float* __restrict__ w5, const float* __restrict__ b5,
                   float* __restrict__ out) {
    __shared__ float sxc[10][3][256];
    __shared__ float sw[1050];
    const int b = blockIdx.y, h = blockIdx.x;
    const int tid = threadIdx.x;
    for (int idx = tid; idx < 1050; idx += 256) sw[idx] = w5[idx];

    float acc = 0.f;
    for (int cb = 0; cb < 50; cb += 10) {
        __syncthreads();
        for (int idx = tid; idx < 10*3*256; idx += 256) {
            int cl = idx / 768, p = (idx >> 8) % 3, col = idx & 255;
            sxc[cl][p][col] =
                g_a4[((b*50 + cb + cl)*64 + ((h - p) & 63))*256 + col];
        }
        __syncthreads();
        for (int cl = 0; cl < 10; cl++) {
            #pragma unroll
            for (int p = 0; p < 3; p++)
                #pragma unroll
                for (int q = 0; q < 7; q++)
                    acc += sw[(cb + cl)*21 + p*7 + q] * sxc[cl][p][(tid - q) & 255];
        }
    }
    float z = acc + b5[0];
    out[(b*64 + h)*256 + tid] = 1.f / (1.f + expf(-z));
}

// ---------------------------------------------------------------------------
extern "C" void kernel_launch(void* const* d_in, const int* in_sizes, int n_in,
                              void* d_out, int out_size) {
    const float* x  = (const float*)d_in[0];
    const float* w1 = (const float*)d_in[1];
    const float* b1 = (const float*)d_in[2];
    const float* w2 = (const float*)d_in[3];
    const float* b2 = (const float*)d_in[4];
    const float* w3 = (const float*)d_in[5];
    const float* b3 = (const float*)d_in[6];
    const float* w4 = (const float*)d_in[7];
    const float* b4 = (const float*)d_in[8];
    const float* w5 = (const float*)d_in[9];
    const float* b5 = (const float*)d_in[10];
    float* out = (float*)d_out;

    k1<<<dim3(8, 32), 256>>>(x, w1, b1);
    k2<<<dim3(16, 32), 256>>>(w2, b2);
    k3<<<800, 256>>>();
    k4<<<dim3(32, 16), 256>>>(w3, b3);
    k5<<<dim3(64, 16), 256>>>(w4, b4);
    k6<<<dim3(64, 16), 256>>>(w5, b5, out);
}

// round 2
// speedup vs baseline: 1.3093x; 1.3093x over previous
#include <cuda_runtime.h>
#include <math.h>

// Intermediate activations (static device globals — no runtime allocation).
__device__ float g_a1[32*50*32*64];    // after L1 (conv+pool+relu)   [32,50,32,64]
__device__ float g_a2[32*50*16*16];    // after L2 (conv+pool+relu)   [32,50,16,16]
__device__ float g_a2c[16*50*16*16];   // after combine               [16,50,16,16]
__device__ float g_a3[16*50*32*64];    // after L3 (up+conv+relu)     [16,50,32,64]
__device__ float g_a4[16*50*64*256];   // after L4 (up+conv+relu)     [16,50,64,256]

// ---------------------------------------------------------------------------
// K1: circular conv1 (1->50, 3x7 on 64x256) + maxpool(2,4) + relu
// grid (8 strips, 32 batch), 256 threads. Strip = 4 pooled rows = 8 conv rows.
// ---------------------------------------------------------------------------
__global__ void k1(const float* __restrict__ x, const float* __restrict__ w1,
                   const float* __restrict__ b1) {
    __shared__ float sx[10][256];
    __shared__ float sw[50*21];
    const int b = blockIdx.y, strip = blockIdx.x;
    const int tid = threadIdx.x;
    const float* xb = x + b*64*256;
    for (int idx = tid; idx < 10*256; idx += 256) {
        int l = idx >> 8, col = idx & 255;
        int row = (strip*8 - 2 + l) & 63;
        sx[l][col] = xb[row*256 + col];
    }
    for (int idx = tid; idx < 1050; idx += 256) sw[idx] = w1[idx];
    __syncthreads();

    const int prl = tid >> 6;          // pooled row within strip 0..3
    const int pw  = tid & 63;          // pooled col 0..63
    float xv[4][10];
    #pragma unroll
    for (int rl = 0; rl < 4; rl++)
        #pragma unroll
        for (int j = 0; j < 10; j++)
            xv[rl][j] = sx[prl*2 + rl][(pw*4 - 6 + j) & 255];

    const int pr = strip*4 + prl;
    for (int co = 0; co < 50; co++) {
        float acc[8];
        #pragma unroll
        for (int i = 0; i < 8; i++) acc[i] = 0.f;
        #pragma unroll
        for (int p = 0; p < 3; p++)
            #pragma unroll
            for (int q = 0; q < 7; q++) {
                float wv = sw[co*21 + p*7 + q];
                #pragma unroll
                for (int dr = 0; dr < 2; dr++)
                    #pragma unroll
                    for (int dc = 0; dc < 4; dc++)
                        acc[dr*4+dc] += wv * xv[dr + 2 - p][dc + 6 - q];
            }
        float m = acc[0];
        #pragma unroll
        for (int i = 1; i < 8; i++) m = fmaxf(m, acc[i]);
        g_a1[((b*50 + co)*32 + pr)*64 + pw] = fmaxf(m + b1[co], 0.f);
    }
}

// ---------------------------------------------------------------------------
// K2: circular conv2 (50->50, 3x7 on 32x64) + maxpool(2,4) + relu
// grid (16 pooled rows, 32 batch), 800 threads = (16 pw, 50 co). No co waste.
// Weights staged through smem in cin-chunks of 5.
// ---------------------------------------------------------------------------
__global__ void k2(const float* __restrict__ w2, const float* __restrict__ b2) {
    __shared__ float sx[5][4][64];      // [cin-chunk][conv row][col]
    __shared__ float sw[50*5*21];       // [co][cin-chunk][tap]
    const int b = blockIdx.y, r = blockIdx.x;
    const int tid = threadIdx.x;
    const int pw = tid & 15, co = tid >> 4;   // co in 0..49 (800 threads)

    float acc[8];
    #pragma unroll
    for (int i = 0; i < 8; i++) acc[i] = 0.f;

    for (int cb = 0; cb < 50; cb += 5) {
        __syncthreads();
        for (int idx = tid; idx < 5*4*64; idx += 800) {
            int cl = idx >> 8, l = (idx >> 6) & 3, col = idx & 63;
            int row = (2*r - 2 + l) & 31;
            sx[cl][l][col] = g_a1[((b*50 + cb + cl)*32 + row)*64 + col];
        }
        for (int idx = tid; idx < 50*5*21; idx += 800) {
            int wo = idx / 105, rem = idx - wo*105;
            sw[idx] = w2[wo*1050 + cb*21 + rem];
        }
        __syncthreads();
        #pragma unroll
        for (int cl = 0; cl < 5; cl++) {
            const float* swc = &sw[co*105 + cl*21];
            #pragma unroll
            for (int p = 0; p < 3; p++) {
                // conv rows needed for this p: l = 2-p (dr=0), 3-p (dr=1)
                float xv0[10], xv1[10];
                #pragma unroll
                for (int j = 0; j < 10; j++) {
                    int c = (pw*4 - 6 + j) & 63;
                    xv0[j] = sx[cl][2 - p][c];
                    xv1[j] = sx[cl][3 - p][c];
                }
                #pragma unroll
                for (int q = 0; q < 7; q++) {
                    float wv = swc[p*7 + q];
                    #pragma unroll
                    for (int dc = 0; dc < 4; dc++) {
                        acc[dc]     += wv * xv0[dc + 6 - q];
                        acc[4 + dc] += wv * xv1[dc + 6 - q];
                    }
                }
            }
        }
    }
    float m = acc[0];
    #pragma unroll
    for (int i = 1; i < 8; i++) m = fmaxf(m, acc[i]);
    g_a2[((b*50 + co)*16 + r)*16 + pw] = fmaxf(m + b2[co], 0.f);
}

// ---------------------------------------------------------------------------
// K3: combine: out[b] = a2[2b] + mean_{hw}(a2[2b+1]).  grid 800 = 16*50.
// ---------------------------------------------------------------------------
__global__ void k3() {
    const int bc = blockIdx.x;
    const int b = bc / 50, c = bc % 50;
    const int t = threadIdx.x;
    const float* ev = g_a2 + ((2*b)*50 + c)*256;
    const float* od = g_a2 + ((2*b + 1)*50 + c)*256;
    __shared__ float red[256];
    red[t] = od[t];
    __syncthreads();
    for (int s = 128; s > 0; s >>= 1) {
        if (t < s) red[t] += red[t + s];
        __syncthreads();
    }
    float mean = red[0] * (1.f/256.f);
    g_a2c[(b*50 + c)*256 + t] = ev[t] + mean;
}

// ---------------------------------------------------------------------------
// K4: zero-upsample(2,4) + circular conv3 (50->50, 3x5 on 32x64) + relu.
// Sparsity: only taps with (h-p) even and (w-q)%4==0 contribute.
// grid (32 h, 16 b), 256 threads; thread t<200 owns (co = t/4, cls = t%4)
// and ALL 16 w-positions of its class -> every weight load feeds 16 FMAs.
// ---------------------------------------------------------------------------
__global__ void k4(const float* __restrict__ w3, const float* __restrict__ b3) {
    __shared__ float sxd[50][2][16];
    const int b = blockIdx.y, h = blockIdx.x;
    const int tid = threadIdx.x;
    const int hodd = h & 1;
    const int pA = hodd ? 1 : 0;
    const int rowA = ((h - pA) & 31) >> 1;
    const int rowB = ((h - 2) & 31) >> 1;
    for (int idx = tid; idx < 1600; idx += 256) {
        int cin = idx >> 5, slot = (idx >> 4) & 1, col = idx & 15;
        int row = slot ? rowB : rowA;
        sxd[cin][slot][col] = g_a2c[((b*50 + cin)*16 + row)*16 + col];
    }
    __syncthreads();

    if (tid < 200) {
        const int co = tid >> 2, cls = tid & 3;
        float acc[16];
        #pragma unroll
        for (int j = 0; j < 16; j++) acc[j] = 0.f;

        #pragma unroll 2
        for (int cin = 0; cin < 50; cin++) {
            const float* wp = w3 + (co*50 + cin)*15;
            // slot A: p = pA
            {
                float xr[16];
                #pragma unroll
                for (int jj = 0; jj < 4; jj++) {
                    float4 v = *(const float4*)&sxd[cin][0][jj*4];
                    xr[jj*4+0] = v.x; xr[jj*4+1] = v.y;
                    xr[jj*4+2] = v.z; xr[jj*4+3] = v.w;
                }
                float w0 = __ldg(&wp[pA*5 + cls]);
                #pragma unroll
                for (int j = 0; j < 16; j++) acc[j] += w0 * xr[j];
                if (cls == 0) {
                    float w1 = __ldg(&wp[pA*5 + 4]);
                    #pragma unroll
                    for (int j = 0; j < 16; j++)
                        acc[j] += w1 * xr[(j + 15) & 15];
                }
            }
            if (!hodd) {   // slot B: p = 2
                float xr[16];
                #pragma unroll
                for (int jj = 0; jj < 4; jj++) {
                    float4 v = *(const float4*)&sxd[cin][1][jj*4];
                    xr[jj*4+0] = v.x; xr[jj*4+1] = v.y;
                    xr[jj*4+2] = v.z; xr[jj*4+3] = v.w;
                }
                float w0 = __ldg(&wp[10 + cls]);
                #pragma unroll
                for (int j = 0; j < 16; j++) acc[j] += w0 * xr[j];
                if (cls == 0) {
                    float w1 = __ldg(&wp[10 + 4]);
                    #pragma unroll
                    for (int j = 0; j < 16; j++)
                        acc[j] += w1 * xr[(j + 15) & 15];
                }
            }
        }
        float bb = b3[co];
        #pragma unroll
        for (int j = 0; j < 16; j++)
            g_a3[((b*50 + co)*32 + h)*64 + cls + 4*j] =
                fmaxf(acc[j] + bb, 0.f);
    }
}

// ---------------------------------------------------------------------------
// K5: zero-upsample(2,4) + circular conv4 (50->50, 3x7 on 64x256) + relu.
// grid (128 = h*2 halves, 16 b), 224 threads; thread t<200 owns
// (co = t/4, cls = t%4) and 32 w-positions of its class in its half.
// Every weight load (L1/L2-resident) feeds 32 FMAs.
// ---------------------------------------------------------------------------
__global__ void k5(const float* __restrict__ w4, const float* __restrict__ b4) {
    __shared__ float sxd[50][2][64];
    const int b = blockIdx.y, hx = blockIdx.x;
    const int h = hx >> 1, h2 = hx & 1;
    const int tid = threadIdx.x;
    const int hodd = h & 1;
    const int pA = hodd ? 1 : 0;
    const int rowA = ((h - pA) & 63) >> 1;
    const int rowB = ((h - 2) & 63) >> 1;
    for (int idx = tid; idx < 6400; idx += 224) {
        int cin = idx >> 7, slot = (idx >> 6) & 1, col = idx & 63;
        int row = slot ? rowB : rowA;
        sxd[cin][slot][col] = g_a3[((b*50 + cin)*32 + row)*64 + col];
    }
    __syncthreads();

    if (tid < 200) {
        const int co = tid >> 2, cls = tid & 3;
        const int bcol = h2*32;
        const int colm = (bcol + 63) & 63;   // bcol-1 mod 64
        float acc[32];
        #pragma unroll
        for (int j = 0; j < 32; j++) acc[j] = 0.f;

        #pragma unroll 2
        for (int cin = 0; cin < 50; cin++) {
            const float* wp = w4 + (co*50 + cin)*21;
            // slot A: p = pA
            {
                float xr[32];
                #pragma unroll
                for (int jj = 0; jj < 8; jj++) {
                    float4 v = *(const float4*)&sxd[cin][0][bcol + jj*4];
                    xr[jj*4+0] = v.x; xr[jj*4+1] = v.y;
                    xr[jj*4+2] = v.z; xr[jj*4+3] = v.w;
                }
                float xm = sxd[cin][0][colm];
                float w0 = __ldg(&wp[pA*7 + cls]);
                #pragma unroll
                for (int j = 0; j < 32; j++) acc[j] += w0 * xr[j];
                if (cls < 3) {
                    float w1 = __ldg(&wp[pA*7 + cls + 4]);
                    acc[0] += w1 * xm;
                    #pragma unroll
                    for (int j = 1; j < 32; j++) acc[j] += w1 * xr[j-1];
                }
            }
            if (!hodd) {   // slot B: p = 2
                float xr[32];
                #pragma unroll
                for (int jj = 0; jj < 8; jj++) {
                    float4 v = *(const float4*)&sxd[cin][1][bcol + jj*4];
                    xr[jj*4+0] = v.x; xr[jj*4+1] = v.y;
                    xr[jj*4+2] = v.z; xr[jj*4+3] = v.w;
                }
                float xm = sxd[cin][1][colm];
                float w0 = __ldg(&wp[14 + cls]);
                #pragma unroll
                for (int j = 0; j < 32; j++) acc[j] += w0 * xr[j];
                if (cls < 3) {
                    float w1 = __ldg(&wp[14 + cls + 4]);
                    acc[0] += w1 * xm;
                    #pragma unroll
                    for (int j = 1; j < 32; j++) acc[j] += w1 * xr[j-1];
                }
            }
        }
        float bb = b4[co];
        #pragma unroll
        for (int j = 0; j < 32; j++)
            g_a4[((b*50 + co)*64 + h)*256 + cls + 4*(bcol + j)] =
                fmaxf(acc[j] + bb, 0.f);
    }
}

// ---------------------------------------------------------------------------
// K6: circular conv5 (50->1, 3x7 on 64x256) + sigmoid.
// grid (64 h, 16 b), 256 threads (w). cin chunked by 10 through smem.
// ---------------------------------------------------------------------------
__global__ void k6(const float* __restrict__ w5, const float* __restrict__ b5,
                   float* __restrict__ out) {
    __shared__ float sxc[10][3][256];
    __shared__ float sw[1050];
    const int b = blockIdx.y, h = blockIdx.x;
    const int tid = threadIdx.x;
    for (int idx = tid; idx < 1050; idx += 256) sw[idx] = w5[idx];

    float acc = 0.f;
    for (int cb = 0; cb < 50; cb += 10) {
        __syncthreads();
        for (int idx = tid; idx < 10*3*256; idx += 256) {
            int cl = idx / 768, p = (idx >> 8) % 3, col = idx & 255;
            sxc[cl][p][col] =
                g_a4[((b*50 + cb + cl)*64 + ((h - p) & 63))*256 + col];
        }
        __syncthreads();
        for (int cl = 0; cl < 10; cl++) {
            #pragma unroll
            for (int p = 0; p < 3; p++)
                #pragma unroll
                for (int q = 0; q < 7; q++)
                    acc += sw[(cb + cl)*21 + p*7 + q] * sxc[cl][p][(tid - q) & 255];
        }
    }
    float z = acc + b5[0];
    out[(b*64 + h)*256 + tid] = 1.f / (1.f + expf(-z));
}

// ---------------------------------------------------------------------------
extern "C" void kernel_launch(void* const* d_in, const int* in_sizes, int n_in,
                              void* d_out, int out_size) {
    const float* x  = (const float*)d_in[0];
    const float* w1 = (const float*)d_in[1];
    const float* b1 = (const float*)d_in[2];
    const float* w2 = (const float*)d_in[3];
    const float* b2 = (const float*)d_in[4];
    const float* w3 = (const float*)d_in[5];
    const float* b3 = (const float*)d_in[6];
    const float* w4 = (const float*)d_in[7];
    const float* b4 = (const float*)d_in[8];
    const float* w5 = (const float*)d_in[9];
    const float* b5 = (const float*)d_in[10];
    float* out = (float*)d_out;

    k1<<<dim3(8, 32), 256>>>(x, w1, b1);
    k2<<<dim3(16, 32), 800>>>(w2, b2);
    k3<<<800, 256>>>();
    k4<<<dim3(32, 16), 256>>>(w3, b3);
    k5<<<dim3(128, 16), 224>>>(w4, b4);
    k6<<<dim3(64, 16), 256>>>(w5, b5, out);
}